// round 12
// baseline (speedup 1.0000x reference)
#include <cuda_runtime.h>
#include <cooperative_groups.h>
#include <math.h>

namespace cg = cooperative_groups;

#define HW 64
#define NP 4096
#define CK 1024          // elements per block
#define RUN 256          // sorted-run length
#define MAXB 32

// per-block partial sums + monotonic ticket (never reset; graph-replay-safe)
__device__ float g_part[MAXB * 8];
__device__ unsigned int g_tick;

__global__ __launch_bounds__(1024, 1) __cluster_dims__(8, 1, 1)
void chamfer_kernel(const float* __restrict__ depth,
                    const float* __restrict__ bnd,
                    float* __restrict__ out,
                    float inv_total, int nblk) {
    __shared__ float sm[NP];          // sort dbuf (first 2048); then search target
    __shared__ float s_sorted[CK];    // this block's 4 sorted 256-runs (DSMEM-visible)
    __shared__ float swarp[32];

    cg::cluster_group cluster = cg::this_cluster();
    const int t    = threadIdx.x;
    const int blk  = blockIdx.x;
    const int rank = (int)cluster.block_rank();   // 0..7
    const int c    = rank & 3;            // chunk quarter
    const int arr  = rank >> 2;           // 0 = sobel(g), 1 = boundary
    const int b    = blk >> 3;            // batch

    // ---- Phase 1: one element per thread ----
    const int e = c * CK + t;
    float v;
    if (arr == 1) {
        v = bnd[b * NP + e];
    } else {
        const float* d = depth + b * NP;
        int y = e >> 6, x = e & 63;
        float p[3][3];
        #pragma unroll
        for (int dy = -1; dy <= 1; dy++)
            #pragma unroll
            for (int dx = -1; dx <= 1; dx++) {
                int yy = y + dy, xx = x + dx;
                bool ok = (yy >= 0) & (yy < HW) & (xx >= 0) & (xx < HW);
                p[dy + 1][dx + 1] = ok ? d[yy * HW + xx] : 0.0f;
            }
        float gx = (p[0][0] - p[0][2]) + 2.0f * (p[1][0] - p[1][2]) + (p[2][0] - p[2][2]);
        float gy = (p[0][0] - p[2][0]) + 2.0f * (p[0][1] - p[2][1]) + (p[0][2] - p[2][2]);
        v = sqrtf(gx * gx + gy * gy + 1e-8f);
    }

    // ---- Phase 2: four independent ascending 256-sorts (group = t>>8) ----
    // Predicates use ti = t&255 (in-group index) — using t would flip direction
    // for odd groups at k=256. Exchanges: j<=16 shfl (in-warp); j=32..128 smem
    // (cross-warp; shfl is a silent no-op there — R8/R9 lesson). 6 smem steps.
    const int ti = t & (RUN - 1);
    int pbuf = 0;
    #pragma unroll
    for (int k = 2; k <= RUN; k <<= 1) {
        #pragma unroll
        for (int j = k >> 1; j >= 1; j >>= 1) {
            bool keepMin = ((ti & j) == 0) == ((ti & k) == 0);
            float o;
            if (j >= 32) {
                float* buf = sm + pbuf * CK;
                buf[t] = v;
                __syncthreads();
                o = buf[t ^ j];      // j<=128 -> partner stays within the group
                pbuf ^= 1;
            } else {
                o = __shfl_xor_sync(0xffffffffu, v, j);
            }
            v = keepMin ? fminf(v, o) : fmaxf(v, o);
        }
    }

    // publish the block's 4 sorted runs (v stays as this thread's query; the
    // query multiset is unchanged and the final sum is permutation-invariant)
    s_sorted[t] = v;

    // ---- Phase 3: cluster barrier (orders smem writes for DSMEM readers) ----
    cluster.sync();

    // ---- Phase 4: pull the OTHER array's 16 sorted runs from peer CTAs ----
    {
        int ch = t >> 8;                    // peer chunk 0..3
        int off = (t & 255) * 4;            // float4 offset within 1024-chunk
        const float* peer = cluster.map_shared_rank(s_sorted, (arr ^ 1) * 4 + ch);
        float4 q = *(const float4*)(peer + off);
        *(float4*)(sm + (ch << 10) + off) = q;
    }
    cluster.sync();   // no CTA exits while peers still read its smem

    // ---- Phase 5: 16-run search, 8 levels each, 16-way ILP ----
    const float x = v;
    float dmin = 3.4e38f;
    #pragma unroll
    for (int r = 0; r < 16; r++) {
        const float* T = sm + (r << 8);
        int pos = 0;                  // branchless lower_bound, saturates at RUN-1
        #pragma unroll
        for (int s = RUN / 2; s >= 1; s >>= 1) {
            if (T[pos + s - 1] < x) pos += s;
        }
        // if x > all of run: pos=RUN-1, T[pos]<x, fabsf = dist to run max
        float dd = fabsf(T[pos] - x);
        if (pos > 0) dd = fminf(dd, x - T[pos - 1]);
        dmin = fminf(dmin, dd);
    }
    float acc = dmin;

    // ---- Phase 6: block reduce; ticket finalize (replay-safe, race-free) ----
    #pragma unroll
    for (int o = 16; o > 0; o >>= 1) acc += __shfl_xor_sync(0xffffffffu, acc, o);
    if ((t & 31) == 0) swarp[t >> 5] = acc;
    __syncthreads();
    if (t < 32) {
        float z = swarp[t];           // exactly 32 warps
        #pragma unroll
        for (int o = 16; o > 0; o >>= 1) z += __shfl_xor_sync(0xffffffffu, z, o);
        if (t == 0) {
            g_part[blk] = z;
            __threadfence();
            unsigned int tk = atomicAdd(&g_tick, 1u);
            if ((tk % (unsigned)nblk) == (unsigned)(nblk - 1)) {
                __threadfence();      // all partials of this launch visible
                float s = 0.0f;
                for (int i2 = 0; i2 < nblk; i2++)
                    s += ((volatile float*)g_part)[i2];
                out[0] = s * inv_total;   // overwrites poison on every replay
            }
        }
    }
}

extern "C" void kernel_launch(void* const* d_in, const int* in_sizes, int n_in,
                              void* d_out, int out_size) {
    const float* depth = (const float*)d_in[0];
    const float* bnd   = (const float*)d_in[1];
    float* out = (float*)d_out;

    int B = in_sizes[0] / NP;
    if (B > MAXB) B = MAXB;
    int nblk = B * 8;                 // multiple of cluster size 8
    float inv_total = 1.0f / (float)(B * NP);

    chamfer_kernel<<<nblk, 1024>>>(depth, bnd, out, inv_total, nblk);
}

// round 13
// speedup vs baseline: 1.1130x; 1.1130x over previous
#include <cuda_runtime.h>
#include <cooperative_groups.h>
#include <math.h>

namespace cg = cooperative_groups;

#define HW 64
#define NP 4096
#define CK 1024          // elements per block (chunk)
#define NB 1024          // buckets per chunk
#define MAXB 32
#define CH_STRIDE 2052   // per-peer-chunk struct: 1024 vals + 1025 off + pad (floats)

// per-block partial sums + monotonic ticket (never reset; graph-replay-safe)
__device__ float g_part[MAXB * 8];
__device__ unsigned int g_tick;

__global__ __launch_bounds__(1024, 1) __cluster_dims__(8, 1, 1)
void chamfer_kernel(const float* __restrict__ depth,
                    const float* __restrict__ bnd,
                    float* __restrict__ out,
                    float inv_total, int nblk) {
    // published (DSMEM-visible) structures
    __shared__ __align__(16) float s_val[CK];      // bucket-sorted values
    __shared__ __align__(16) int   s_off[NB + 3];  // bucket segment offsets (+sentinel)
    __shared__ float s_meta[2];                    // mn, scale
    // scratch
    __shared__ int   s_cnt[NB];                    // histogram, then scatter cursors
    __shared__ float s_red[64];
    __shared__ int   s_wsum[32];
    __shared__ float swarp[32];
    // local copies of 4 peer chunk structs
    __shared__ __align__(16) float s_peer[4 * CH_STRIDE];
    __shared__ float s_pmeta[8];

    cg::cluster_group cluster = cg::this_cluster();
    const int t    = threadIdx.x;
    const int lane = t & 31, wid = t >> 5;
    const int blk  = blockIdx.x;
    const int rank = (int)cluster.block_rank();   // 0..7
    const int c    = rank & 3;            // chunk quarter
    const int arr  = rank >> 2;           // 0 = sobel(g), 1 = boundary
    const int b    = blk >> 3;            // batch

    // ---- Phase 1: one element per thread ----
    const int e = c * CK + t;
    float v;
    if (arr == 1) {
        v = bnd[b * NP + e];
    } else {
        const float* d = depth + b * NP;
        int y = e >> 6, x = e & 63;
        float p[3][3];
        #pragma unroll
        for (int dy = -1; dy <= 1; dy++)
            #pragma unroll
            for (int dx = -1; dx <= 1; dx++) {
                int yy = y + dy, xx = x + dx;
                bool ok = (yy >= 0) & (yy < HW) & (xx >= 0) & (xx < HW);
                p[dy + 1][dx + 1] = ok ? d[yy * HW + xx] : 0.0f;
            }
        float gx = (p[0][0] - p[0][2]) + 2.0f * (p[1][0] - p[1][2]) + (p[2][0] - p[2][2]);
        float gy = (p[0][0] - p[2][0]) + 2.0f * (p[0][1] - p[2][1]) + (p[0][2] - p[2][2]);
        v = sqrtf(gx * gx + gy * gy + 1e-8f);
    }

    // ---- Phase 2: bucket (counting) sort of the 1024-chunk ----
    // 2a: min/max reduce
    float mn = v, mx = v;
    #pragma unroll
    for (int o = 16; o > 0; o >>= 1) {
        mn = fminf(mn, __shfl_xor_sync(0xffffffffu, mn, o));
        mx = fmaxf(mx, __shfl_xor_sync(0xffffffffu, mx, o));
    }
    if (lane == 0) { s_red[wid] = mn; s_red[32 + wid] = mx; }
    s_cnt[t] = 0;                       // clear histogram (NB == CK)
    __syncthreads();
    if (t < 32) {
        float a = s_red[t], z = s_red[32 + t];
        #pragma unroll
        for (int o = 16; o > 0; o >>= 1) {
            a = fminf(a, __shfl_xor_sync(0xffffffffu, a, o));
            z = fmaxf(z, __shfl_xor_sync(0xffffffffu, z, o));
        }
        if (t == 0) {
            float range = fmaxf(z - a, 1e-30f);
            s_meta[0] = a;
            s_meta[1] = (float)NB / range;
        }
    }
    __syncthreads();
    const float mnv = s_meta[0], sc = s_meta[1];

    // 2b: histogram
    int bkt = (int)((v - mnv) * sc);
    bkt = bkt < 0 ? 0 : (bkt > NB - 1 ? NB - 1 : bkt);
    atomicAdd(&s_cnt[bkt], 1);
    __syncthreads();

    // 2c: exclusive scan of s_cnt -> s_off (3-level: warp shfl + warp sums)
    int cval = s_cnt[t];
    int inc = cval;
    #pragma unroll
    for (int o = 1; o < 32; o <<= 1) {
        int u = __shfl_up_sync(0xffffffffu, inc, o);
        if (lane >= o) inc += u;
    }
    if (lane == 31) s_wsum[wid] = inc;
    __syncthreads();
    if (t < 32) {
        int w = s_wsum[t];
        #pragma unroll
        for (int o = 1; o < 32; o <<= 1) {
            int u = __shfl_up_sync(0xffffffffu, w, o);
            if (t >= o) w += u;
        }
        s_wsum[t] = w;                   // inclusive warp-sum scan
    }
    __syncthreads();
    int off = inc - cval + (wid ? s_wsum[wid - 1] : 0);
    s_off[t] = off;
    if (t == CK - 1) s_off[NB] = off + cval;   // == 1024
    s_cnt[t] = off;                             // scatter cursors
    __syncthreads();

    // 2d: scatter (within-bucket order arbitrary — result is order-invariant)
    int pos = atomicAdd(&s_cnt[bkt], 1);
    s_val[pos] = v;

    // ---- Phase 3: cluster barrier (publish s_val/s_off/s_meta) ----
    cluster.sync();

    // ---- Phase 4: copy the OTHER array's 4 chunk structs via DSMEM ----
    {
        int ch = t >> 8;                       // 0..3
        int q  = t & 255;
        int peer = (arr ^ 1) * 4 + ch;
        const float* pval = cluster.map_shared_rank(s_val,  peer);
        const int*   poff = cluster.map_shared_rank(s_off,  peer);
        const float* pmet = cluster.map_shared_rank(s_meta, peer);
        float* dstv = s_peer + ch * CH_STRIDE;
        int*   dsto = (int*)(dstv + CK);
        *(float4*)(dstv + q * 4) = *(const float4*)(pval + q * 4);
        *(int4*)(dsto + q * 4)   = *(const int4*)(poff + q * 4);
        if (q == 0) {
            dsto[NB] = CK;                     // sentinel (always 1024)
            s_pmeta[2 * ch]     = pmet[0];
            s_pmeta[2 * ch + 1] = pmet[1];
        }
    }
    // copy done block-wide AND no CTA exits while peers still read its smem
    cluster.sync();

    // ---- Phase 5: bucket-lookup nearest-neighbor, 4 chunks ----
    const float x = v;
    float dmin = 3.4e38f;
    #pragma unroll
    for (int ch = 0; ch < 4; ch++) {
        const float* V = s_peer + ch * CH_STRIDE;
        const int*   O = (const int*)(V + CK);
        float cmn = s_pmeta[2 * ch], cs = s_pmeta[2 * ch + 1];
        int bq = (int)((x - cmn) * cs);
        bq = bq < 0 ? 0 : (bq > NB - 1 ? NB - 1 : bq);
        int lo = O[bq], hi = O[bq + 1];
        // own bucket
        for (int i = lo; i < hi; i++) dmin = fminf(dmin, fabsf(V[i] - x));
        // nearest nonempty bucket below: V[lo-1] is its max; scan it fully
        if (lo > 0) {
            float u = V[lo - 1];
            int qb = (int)((u - cmn) * cs);
            qb = qb < 0 ? 0 : (qb > NB - 1 ? NB - 1 : qb);
            int ql = O[qb];
            for (int i = ql; i < lo; i++) dmin = fminf(dmin, fabsf(V[i] - x));
        }
        // nearest nonempty bucket above: V[hi] is its min; scan it fully
        if (hi < CK) {
            float w = V[hi];
            int rb = (int)((w - cmn) * cs);
            rb = rb < 0 ? 0 : (rb > NB - 1 ? NB - 1 : rb);
            int rh = O[rb + 1];
            for (int i = hi; i < rh; i++) dmin = fminf(dmin, fabsf(V[i] - x));
        }
    }
    float acc = dmin;

    // ---- Phase 6: block reduce; ticket finalize (replay-safe, race-free) ----
    #pragma unroll
    for (int o = 16; o > 0; o >>= 1) acc += __shfl_xor_sync(0xffffffffu, acc, o);
    if (lane == 0) swarp[wid] = acc;
    __syncthreads();
    if (t < 32) {
        float z = swarp[t];           // exactly 32 warps
        #pragma unroll
        for (int o = 16; o > 0; o >>= 1) z += __shfl_xor_sync(0xffffffffu, z, o);
        if (t == 0) {
            g_part[blk] = z;
            __threadfence();
            unsigned int tk = atomicAdd(&g_tick, 1u);
            if ((tk % (unsigned)nblk) == (unsigned)(nblk - 1)) {
                __threadfence();      // all partials of this launch visible
                float s = 0.0f;
                for (int i2 = 0; i2 < nblk; i2++)
                    s += ((volatile float*)g_part)[i2];
                out[0] = s * inv_total;   // overwrites poison on every replay
            }
        }
    }
}

extern "C" void kernel_launch(void* const* d_in, const int* in_sizes, int n_in,
                              void* d_out, int out_size) {
    const float* depth = (const float*)d_in[0];
    const float* bnd   = (const float*)d_in[1];
    float* out = (float*)d_out;

    int B = in_sizes[0] / NP;
    if (B > MAXB) B = MAXB;
    int nblk = B * 8;                 // multiple of cluster size 8
    float inv_total = 1.0f / (float)(B * NP);

    chamfer_kernel<<<nblk, 1024>>>(depth, bnd, out, inv_total, nblk);
}

// round 14
// speedup vs baseline: 1.1604x; 1.0426x over previous
#include <cuda_runtime.h>
#include <cooperative_groups.h>
#include <math.h>

namespace cg = cooperative_groups;

#define HW 64
#define NP 4096
#define CK 1024          // elements per block (chunk)
#define THREADS 256      // 4 elements per thread
#define MAXB 32

// per-block partial sums + monotonic ticket (never reset; graph-replay-safe)
__device__ float g_part[MAXB * 8];
__device__ unsigned int g_tick;

__device__ __forceinline__ void ce(float& a, float& b, bool up) {
    float lo = fminf(a, b), hi = fmaxf(a, b);
    a = up ? lo : hi;
    b = up ? hi : lo;
}

__global__ __launch_bounds__(THREADS, 1) __cluster_dims__(8, 1, 1)
void chamfer_kernel(const float* __restrict__ depth,
                    const float* __restrict__ bnd,
                    float* __restrict__ out,
                    float inv_total, int nblk) {
    __shared__ __align__(16) float dbuf[2 * CK];   // sort ping-pong
    __shared__ __align__(16) float s_sorted[CK];   // published sorted chunk (DSMEM)
    __shared__ __align__(16) float s_peer[NP];     // other array's 4 sorted chunks
    __shared__ float swarp[8];

    cg::cluster_group cluster = cg::this_cluster();
    const int t    = threadIdx.x;
    const int lane = t & 31, wid = t >> 5;
    const int blk  = blockIdx.x;
    const int rank = (int)cluster.block_rank();   // 0..7
    const int c    = rank & 3;            // chunk quarter
    const int arr  = rank >> 2;           // 0 = sobel(g), 1 = boundary
    const int b    = blk >> 3;            // batch

    const int i0 = 4 * t;                 // first owned element within chunk
    const int e0 = c * CK + i0;           // within batch array

    // ---- Phase 1: four elements per thread ----
    float w[4];
    if (arr == 1) {
        float4 q = *(const float4*)(bnd + b * NP + e0);
        w[0] = q.x; w[1] = q.y; w[2] = q.z; w[3] = q.w;
    } else {
        const float* d = depth + b * NP;
        int y = e0 >> 6, x0 = e0 & 63;    // x0 multiple of 4
        float p[3][6];                    // rows y-1..y+1, cols x0-1..x0+4
        #pragma unroll
        for (int ry = 0; ry < 3; ry++) {
            int yy = y + ry - 1;
            bool yok = (yy >= 0) & (yy < HW);
            #pragma unroll
            for (int cx = 0; cx < 6; cx++) {
                int xx = x0 + cx - 1;
                bool ok = yok & (xx >= 0) & (xx < HW);
                p[ry][cx] = ok ? d[yy * HW + xx] : 0.0f;
            }
        }
        #pragma unroll
        for (int m = 0; m < 4; m++) {
            float gx = (p[0][m] - p[0][m + 2]) + 2.0f * (p[1][m] - p[1][m + 2]) + (p[2][m] - p[2][m + 2]);
            float gy = (p[0][m] + 2.0f * p[0][m + 1] + p[0][m + 2])
                     - (p[2][m] + 2.0f * p[2][m + 1] + p[2][m + 2]);
            w[m] = sqrtf(gx * gx + gy * gy + 1e-8f);
        }
    }

    // ---- Phase 2: ascending bitonic sort of 1024, 4 elems/thread ----
    // j>=128: smem float4 exchange (cross-warp; 6 steps, dbuf, 1 bar/step).
    // j=4..64: shfl, lane distance j/4 <= 16 (in-warp). j=2,1: in-thread.
    int pbuf = 0;
    #pragma unroll
    for (int k = 2; k <= CK; k <<= 1) {
        #pragma unroll
        for (int j = k >> 1; j >= 1; j >>= 1) {
            if (j >= 128) {
                float* buf = dbuf + pbuf * CK;
                *(float4*)&buf[i0] = make_float4(w[0], w[1], w[2], w[3]);
                __syncthreads();
                bool keepMin = ((i0 & j) == 0) == ((i0 & k) == 0);
                float4 o = *(float4*)&buf[i0 ^ j];   // j multiple of 4 -> aligned
                w[0] = keepMin ? fminf(w[0], o.x) : fmaxf(w[0], o.x);
                w[1] = keepMin ? fminf(w[1], o.y) : fmaxf(w[1], o.y);
                w[2] = keepMin ? fminf(w[2], o.z) : fmaxf(w[2], o.z);
                w[3] = keepMin ? fminf(w[3], o.w) : fmaxf(w[3], o.w);
                pbuf ^= 1;
            } else if (j >= 4) {
                bool keepMin = ((i0 & j) == 0) == ((i0 & k) == 0);
                #pragma unroll
                for (int m = 0; m < 4; m++) {
                    float o = __shfl_xor_sync(0xffffffffu, w[m], j >> 2);
                    w[m] = keepMin ? fminf(w[m], o) : fmaxf(w[m], o);
                }
            } else if (j == 2) {           // k >= 4: direction uniform in-thread
                bool up = ((i0 & k) == 0);
                ce(w[0], w[2], up);
                ce(w[1], w[3], up);
            } else {                        // j == 1
                if (k == 2) {               // pairs have opposite directions
                    ce(w[0], w[1], true);   // elem 0: i&2==0 -> asc
                    ce(w[2], w[3], false);  // elem 2: i&2==2 -> desc
                } else {
                    bool up = ((i0 & k) == 0);
                    ce(w[0], w[1], up);
                    ce(w[2], w[3], up);
                }
            }
        }
    }

    // publish sorted chunk (w[] stays as this thread's 4 queries; multiset
    // unchanged, final sum permutation-invariant)
    *(float4*)&s_sorted[i0] = make_float4(w[0], w[1], w[2], w[3]);

    // ---- Phase 3: cluster barrier (orders smem writes for DSMEM readers) ----
    cluster.sync();

    // ---- Phase 4: pull the OTHER array's 4 sorted chunks via DSMEM ----
    #pragma unroll
    for (int ch = 0; ch < 4; ch++) {
        const float* peer = cluster.map_shared_rank(s_sorted, (arr ^ 1) * 4 + ch);
        float4 q = *(const float4*)(peer + i0);
        *(float4*)(s_peer + (ch << 10) + i0) = q;
    }
    cluster.sync();   // no CTA exits while peers still read its smem

    // ---- Phase 5: 16 interleaved searches (4 queries x 4 chunks, 10 levels) ----
    float acc = 0.0f;
    #pragma unroll
    for (int m = 0; m < 4; m++) {
        const float x = w[m];
        float dmin = 3.4e38f;
        #pragma unroll
        for (int ch = 0; ch < 4; ch++) {
            const float* T = s_peer + (ch << 10);
            int pos = 0;                  // branchless lower_bound, saturates at CK-1
            #pragma unroll
            for (int s = CK / 2; s >= 1; s >>= 1) {
                if (T[pos + s - 1] < x) pos += s;
            }
            // x > all of chunk: pos=CK-1, T[pos]<x, fabsf = dist to chunk max
            float dd = fabsf(T[pos] - x);
            if (pos > 0) dd = fminf(dd, x - T[pos - 1]);
            dmin = fminf(dmin, dd);
        }
        acc += dmin;
    }

    // ---- Phase 6: block reduce (8 warps); ticket finalize (replay-safe) ----
    #pragma unroll
    for (int o = 16; o > 0; o >>= 1) acc += __shfl_xor_sync(0xffffffffu, acc, o);
    if (lane == 0) swarp[wid] = acc;
    __syncthreads();
    if (t < 32) {
        float z = (t < 8) ? swarp[t] : 0.0f;
        #pragma unroll
        for (int o = 4; o > 0; o >>= 1) z += __shfl_xor_sync(0xffffffffu, z, o);
        if (t == 0) {
            g_part[blk] = z;
            __threadfence();
            unsigned int tk = atomicAdd(&g_tick, 1u);
            if ((tk % (unsigned)nblk) == (unsigned)(nblk - 1)) {
                __threadfence();      // all partials of this launch visible
                float s = 0.0f;
                for (int i2 = 0; i2 < nblk; i2++)
                    s += ((volatile float*)g_part)[i2];
                out[0] = s * inv_total;   // overwrites poison on every replay
            }
        }
    }
}

extern "C" void kernel_launch(void* const* d_in, const int* in_sizes, int n_in,
                              void* d_out, int out_size) {
    const float* depth = (const float*)d_in[0];
    const float* bnd   = (const float*)d_in[1];
    float* out = (float*)d_out;

    int B = in_sizes[0] / NP;
    if (B > MAXB) B = MAXB;
    int nblk = B * 8;                 // multiple of cluster size 8
    float inv_total = 1.0f / (float)(B * NP);

    chamfer_kernel<<<nblk, THREADS>>>(depth, bnd, out, inv_total, nblk);
}